// round 1
// baseline (speedup 1.0000x reference)
#include <cuda_runtime.h>

// Problem constants
#define NC    188   // nodes
#define PF    16    // features per node
#define HID   128   // hidden
#define H2    64    // hidden/2
#define DE    5     // edge effect dim
#define DOUT  6     // object output dim
#define NT    5     // targets
#define BATCH 32
#define TPB   192   // 6 warps; 187 edges per block

// Scratch for object MLP outputs O[B][N][DOUT]
__device__ float g_O[BATCH * NC * DOUT];

// ---- packed f32x2 helpers ----
__device__ __forceinline__ unsigned long long pk2(float lo, float hi) {
    unsigned long long r;
    asm("mov.b64 %0, {%1, %2};" : "=l"(r) : "f"(lo), "f"(hi));
    return r;
}
__device__ __forceinline__ float2 upk2(unsigned long long v) {
    float2 f;
    asm("mov.b64 {%0, %1}, %2;" : "=f"(f.x), "=f"(f.y) : "l"(v));
    return f;
}
__device__ __forceinline__ void fma2(unsigned long long& d,
                                     unsigned long long a,
                                     unsigned long long b) {
    asm("fma.rn.f32x2 %0, %1, %2, %0;" : "+l"(d) : "l"(a), "l"(b));
}

// ============================================================================
// Kernel A: one block per (receiver node r, batch b).
//   - 187 edges (all with receiver r) through the edge MLP (fr1/fr2/fr3)
//   - block-local reduction -> Ebar[b][r][0:5]   (deterministic, no atomics)
//   - fused object MLP (fo1/fo2/fo3) for node (b, r) -> g_O
// ============================================================================
__global__ void __launch_bounds__(TPB, 2) edge_obj_kernel(
    const float* __restrict__ x,
    const float* __restrict__ fr1_w, const float* __restrict__ fr1_b,
    const float* __restrict__ fr2_w, const float* __restrict__ fr2_b,
    const float* __restrict__ fr3_w, const float* __restrict__ fr3_b,
    const float* __restrict__ fo1_w, const float* __restrict__ fo1_b,
    const float* __restrict__ fo2_w, const float* __restrict__ fo2_b,
    const float* __restrict__ fo3_w, const float* __restrict__ fo3_b)
{
    // sender-half of W1, transposed: SW1S[c*16 + m] = fr1_w[(16+m)*128 + c]
    __shared__ __align__(16) float SW1S[HID * 16];   //  8 KB
    __shared__ __align__(16) float SW2[HID * H2];    // 32 KB (row i contiguous)
    __shared__ float SW3T[DE * H2];                  // fr3 transposed
    __shared__ float SB2[H2];
    __shared__ float SB3[8];
    __shared__ float SXR[PF];                        // receiver features
    __shared__ float SDOTR[HID];                     // b1 + xr . W1[0:16, :]
    __shared__ float SRED[6 * DE];                   // per-warp partials
    __shared__ float SEBAR[8];
    __shared__ float SH1[HID];
    __shared__ float SH2v[H2];

    const int r   = blockIdx.x;
    const int b   = blockIdx.y;
    const int tid = threadIdx.x;

    // ---- cooperative weight staging ----
    for (int idx = tid; idx < HID * 16; idx += TPB) {
        int m = idx >> 7;          // 0..15 (sender feature)
        int c = idx & 127;         // hidden unit
        SW1S[c * 16 + m] = fr1_w[(PF + m) * HID + c];
    }
    for (int idx = tid; idx < HID * H2; idx += TPB) SW2[idx] = fr2_w[idx];
    for (int idx = tid; idx < H2 * DE; idx += TPB) {
        int i = idx / DE, k = idx % DE;
        SW3T[k * H2 + i] = fr3_w[idx];
    }
    if (tid < H2) SB2[tid] = fr2_b[tid];
    if (tid < DE) SB3[tid] = fr3_b[tid];
    if (tid < PF) SXR[tid] = x[((size_t)b * NC + r) * PF + tid];
    __syncthreads();

    // ---- receiver-half dot, shared across all 187 edges of this block ----
    if (tid < HID) {
        float acc = fr1_b[tid];
        #pragma unroll
        for (int m = 0; m < PF; m++)
            acc = fmaf(SXR[m], fr1_w[m * HID + tid], acc);
        SDOTR[tid] = acc;
    }
    __syncthreads();

    // ---- edge MLP: thread tid handles edge j = tid (sender s) ----
    float Ek[DE] = {0.f, 0.f, 0.f, 0.f, 0.f};
    if (tid < NC - 1) {
        const int s = tid + (tid >= r);
        const float4* xsp =
            reinterpret_cast<const float4*>(x + ((size_t)b * NC + s) * PF);
        float4 v0 = xsp[0], v1 = xsp[1], v2 = xsp[2], v3 = xsp[3];
        unsigned long long es[8];
        es[0] = pk2(v0.x, v0.y); es[1] = pk2(v0.z, v0.w);
        es[2] = pk2(v1.x, v1.y); es[3] = pk2(v1.z, v1.w);
        es[4] = pk2(v2.x, v2.y); es[5] = pk2(v2.z, v2.w);
        es[6] = pk2(v3.x, v3.y); es[7] = pk2(v3.z, v3.w);

        // h2 accumulators, packed pairs, init with fr2 bias
        unsigned long long acc2[H2 / 2];
        #pragma unroll
        for (int q = 0; q < H2 / 2; q++)
            acc2[q] = pk2(SB2[2 * q], SB2[2 * q + 1]);

        #pragma unroll 2
        for (int i = 0; i < HID; i++) {
            // sender half-dot (16 MACs as 8 packed FMAs, 2 chains)
            const ulonglong2* w1 =
                reinterpret_cast<const ulonglong2*>(SW1S + i * 16);
            unsigned long long sA = pk2(0.f, 0.f), sB = pk2(0.f, 0.f);
            #pragma unroll
            for (int q = 0; q < 4; q++) {
                ulonglong2 w = w1[q];
                fma2(sA, es[2 * q],     w.x);
                fma2(sB, es[2 * q + 1], w.y);
            }
            float2 fa = upk2(sA), fb = upk2(sB);
            float h1 = SDOTR[i] + ((fa.x + fb.x) + (fa.y + fb.y));
            h1 = fmaxf(h1, 0.f);

            // rank-1 update of h2 accumulators (64 MACs as 32 packed FMAs)
            unsigned long long hh = pk2(h1, h1);
            const ulonglong2* w2 =
                reinterpret_cast<const ulonglong2*>(SW2 + i * H2);
            #pragma unroll
            for (int q = 0; q < 16; q++) {
                ulonglong2 w = w2[q];
                fma2(acc2[2 * q],     hh, w.x);
                fma2(acc2[2 * q + 1], hh, w.y);
            }
        }

        // relu(h2) then fr3 -> E (5 outputs)
        float h2f[H2];
        #pragma unroll
        for (int q = 0; q < H2 / 2; q++) {
            float2 f = upk2(acc2[q]);
            h2f[2 * q]     = fmaxf(f.x, 0.f);
            h2f[2 * q + 1] = fmaxf(f.y, 0.f);
        }
        #pragma unroll
        for (int k = 0; k < DE; k++) {
            float e = SB3[k];
            #pragma unroll
            for (int i2 = 0; i2 < H2; i2++)
                e = fmaf(h2f[i2], SW3T[k * H2 + i2], e);
            Ek[k] = fmaxf(e, 0.f);
        }
    }

    // ---- deterministic block reduction of E over the 187 edges ----
    const int lane = tid & 31, warp = tid >> 5;
    #pragma unroll
    for (int k = 0; k < DE; k++) {
        float v = Ek[k];
        #pragma unroll
        for (int off = 16; off > 0; off >>= 1)
            v += __shfl_down_sync(0xffffffffu, v, off);
        if (lane == 0) SRED[warp * DE + k] = v;
    }
    __syncthreads();
    if (tid < DE) {
        float e = 0.f;
        #pragma unroll
        for (int w = 0; w < 6; w++) e += SRED[w * DE + tid];
        SEBAR[tid] = e;
    }
    __syncthreads();

    // ---- fused object MLP for node (b, r): c = [x_r (16), Ebar (5)] ----
    if (tid < HID) {
        float a = fo1_b[tid];
        #pragma unroll
        for (int m = 0; m < PF; m++)
            a = fmaf(SXR[m], fo1_w[m * HID + tid], a);
        #pragma unroll
        for (int m = 0; m < DE; m++)
            a = fmaf(SEBAR[m], fo1_w[(PF + m) * HID + tid], a);
        SH1[tid] = fmaxf(a, 0.f);
    }
    __syncthreads();
    if (tid < H2) {
        float a = fo2_b[tid];
        #pragma unroll 8
        for (int m = 0; m < HID; m++)
            a = fmaf(SH1[m], fo2_w[m * H2 + tid], a);
        SH2v[tid] = fmaxf(a, 0.f);
    }
    __syncthreads();
    if (tid < DOUT) {
        float a = fo3_b[tid];
        #pragma unroll
        for (int m = 0; m < H2; m++)
            a = fmaf(SH2v[m], fo3_w[m * DOUT + tid], a);
        g_O[((size_t)b * NC + r) * DOUT + tid] = fmaxf(a, 0.f);
    }
}

// ============================================================================
// Kernel B: per-batch FC head. One block per batch row.
// ============================================================================
__global__ void __launch_bounds__(HID) fc_kernel(
    const float* __restrict__ fc1_w, const float* __restrict__ fc1_b,
    const float* __restrict__ fc2_w, const float* __restrict__ fc2_b,
    const float* __restrict__ fc3_w, const float* __restrict__ fc3_b,
    float* __restrict__ out)
{
    __shared__ float sO[NC * DOUT];   // 1128
    __shared__ float sh1[HID];
    __shared__ float sh2[H2];
    const int b = blockIdx.x, tid = threadIdx.x;

    for (int idx = tid; idx < NC * DOUT; idx += HID)
        sO[idx] = g_O[(size_t)b * NC * DOUT + idx];
    __syncthreads();

    float acc = fc1_b[tid];
    #pragma unroll 4
    for (int m = 0; m < NC * DOUT; m++)
        acc = fmaf(sO[m], fc1_w[m * HID + tid], acc);
    sh1[tid] = fmaxf(acc, 0.f);
    __syncthreads();

    if (tid < H2) {
        float a2 = fc2_b[tid];
        #pragma unroll 4
        for (int m = 0; m < HID; m++)
            a2 = fmaf(sh1[m], fc2_w[m * H2 + tid], a2);
        sh2[tid] = fmaxf(a2, 0.f);
    }
    __syncthreads();

    if (tid < NT) {
        float a3 = fc3_b[tid];
        #pragma unroll
        for (int m = 0; m < H2; m++)
            a3 = fmaf(sh2[m], fc3_w[m * NT + tid], a3);
        out[b * NT + tid] = a3;
    }
}

// ============================================================================
// Launch
// ============================================================================
extern "C" void kernel_launch(void* const* d_in, const int* in_sizes, int n_in,
                              void* d_out, int out_size) {
    const float* x     = (const float*)d_in[0];
    const float* fr1_w = (const float*)d_in[1];
    const float* fr1_b = (const float*)d_in[2];
    const float* fr2_w = (const float*)d_in[3];
    const float* fr2_b = (const float*)d_in[4];
    const float* fr3_w = (const float*)d_in[5];
    const float* fr3_b = (const float*)d_in[6];
    const float* fo1_w = (const float*)d_in[7];
    const float* fo1_b = (const float*)d_in[8];
    const float* fo2_w = (const float*)d_in[9];
    const float* fo2_b = (const float*)d_in[10];
    const float* fo3_w = (const float*)d_in[11];
    const float* fo3_b = (const float*)d_in[12];
    const float* fc1_w = (const float*)d_in[13];
    const float* fc1_b = (const float*)d_in[14];
    const float* fc2_w = (const float*)d_in[15];
    const float* fc2_b = (const float*)d_in[16];
    const float* fc3_w = (const float*)d_in[17];
    const float* fc3_b = (const float*)d_in[18];
    float* out = (float*)d_out;

    dim3 grid(NC, BATCH);
    edge_obj_kernel<<<grid, TPB>>>(x,
                                   fr1_w, fr1_b, fr2_w, fr2_b, fr3_w, fr3_b,
                                   fo1_w, fo1_b, fo2_w, fo2_b, fo3_w, fo3_b);
    fc_kernel<<<BATCH, HID>>>(fc1_w, fc1_b, fc2_w, fc2_b, fc3_w, fc3_b, out);
}

// round 2
// speedup vs baseline: 1.1546x; 1.1546x over previous
#include <cuda_runtime.h>

// Problem constants
#define NC    188   // nodes
#define PF    16    // features per node
#define HID   128   // hidden
#define H2    64    // hidden/2
#define DE    5     // edge effect dim
#define DOUT  6     // object output dim
#define NT    5     // targets
#define BATCH 32
#define TPB   192   // 6 warps; 187 edges per block
#define DSP   192   // padded row length for DS (188 -> 192, float4-friendly)
#define CH    16    // i-chunk staged in smem per step

// Scratch
__device__ float g_O[BATCH * NC * DOUT];
__device__ float g_DR[BATCH * NC * HID];     // b1 + xr . W1[0:16,:]   [b][r][i]
__device__ float g_DS[BATCH * HID * DSP];    // xs . W1[16:32,:]        [b][i][s]

// ---- packed f32x2 helpers ----
__device__ __forceinline__ unsigned long long pk2(float lo, float hi) {
    unsigned long long r;
    asm("mov.b64 %0, {%1, %2};" : "=l"(r) : "f"(lo), "f"(hi));
    return r;
}
__device__ __forceinline__ float2 upk2(unsigned long long v) {
    float2 f;
    asm("mov.b64 {%0, %1}, %2;" : "=f"(f.x), "=f"(f.y) : "l"(v));
    return f;
}
__device__ __forceinline__ void fma2(unsigned long long& d,
                                     unsigned long long a,
                                     unsigned long long b) {
    asm("fma.rn.f32x2 %0, %1, %2, %0;" : "+l"(d) : "l"(a), "l"(b));
}

// ============================================================================
// Kernel P: per-node layer-1 half-dots. grid (NC, BATCH), 128 threads.
//   DR[b][n][i] = fr1_b[i] + x[b,n,:] . fr1_w[0:16, i]
//   DS[b][i][n] =            x[b,n,:] . fr1_w[16:32, i]
// ============================================================================
__global__ void __launch_bounds__(HID) precompute_kernel(
    const float* __restrict__ x,
    const float* __restrict__ fr1_w, const float* __restrict__ fr1_b)
{
    __shared__ float SX[PF];
    const int n = blockIdx.x, b = blockIdx.y, i = threadIdx.x;
    if (i < PF) SX[i] = x[((size_t)b * NC + n) * PF + i];
    __syncthreads();
    float dr = fr1_b[i], ds = 0.f;
    #pragma unroll
    for (int m = 0; m < PF; m++) {
        float xm = SX[m];
        dr = fmaf(xm, fr1_w[m * HID + i], dr);
        ds = fmaf(xm, fr1_w[(PF + m) * HID + i], ds);
    }
    g_DR[((size_t)b * NC + n) * HID + i] = dr;
    g_DS[((size_t)b * HID + i) * DSP + n] = ds;
}

// ============================================================================
// Kernel A: one block per (receiver r, batch b).
//   layer1 per edge = relu(DR[i] + DS[i][s])  (precomputed half-dots)
//   layer2 rank-1 accumulated into packed f32x2 registers
//   layer3 + deterministic block reduction -> Ebar
//   fused object MLP -> g_O
// ============================================================================
__global__ void __launch_bounds__(TPB, 2) edge_obj_kernel(
    const float* __restrict__ x,
    const float* __restrict__ fr2_w, const float* __restrict__ fr2_b,
    const float* __restrict__ fr3_w, const float* __restrict__ fr3_b,
    const float* __restrict__ fo1_w, const float* __restrict__ fo1_b,
    const float* __restrict__ fo2_w, const float* __restrict__ fo2_b,
    const float* __restrict__ fo3_w, const float* __restrict__ fo3_b)
{
    __shared__ __align__(16) float SW2[HID * H2];    // 32 KB, row i contiguous
    __shared__ __align__(16) float SDS[CH * DSP];    // 12 KB chunk of DS
    __shared__ float SW3T[DE * H2];                  // fr3 transposed
    __shared__ float SDR[HID];
    __shared__ float SB2[H2];
    __shared__ float SB3[8];
    __shared__ float SXR[PF];
    __shared__ float SRED[6 * DE];
    __shared__ float SEBAR[8];
    __shared__ float SH1[HID];
    __shared__ float SH2v[H2];

    const int r   = blockIdx.x;
    const int b   = blockIdx.y;
    const int tid = threadIdx.x;

    // ---- staging ----
    #pragma unroll 4
    for (int idx = tid; idx < HID * H2; idx += TPB) SW2[idx] = fr2_w[idx];
    for (int idx = tid; idx < H2 * DE; idx += TPB) {
        int i = idx / DE, k = idx % DE;
        SW3T[k * H2 + i] = fr3_w[idx];
    }
    if (tid < H2)  SB2[tid] = fr2_b[tid];
    if (tid < DE)  SB3[tid] = fr3_b[tid];
    if (tid < PF)  SXR[tid] = x[((size_t)b * NC + r) * PF + tid];
    if (tid < HID) SDR[tid] = g_DR[((size_t)b * NC + r) * HID + tid];
    __syncthreads();

    const int sidx = tid + (tid >= r);       // sender index for this thread
    const bool active = (tid < NC - 1);

    // h2 accumulators (packed pairs), init with fr2 bias
    unsigned long long acc2[H2 / 2];
    #pragma unroll
    for (int q = 0; q < H2 / 2; q++)
        acc2[q] = pk2(SB2[2 * q], SB2[2 * q + 1]);

    // ---- main loop over i in chunks of CH ----
    for (int c = 0; c < HID / CH; c++) {
        __syncthreads();
        // coalesced stage of DS rows [c*CH, c*CH+CH)
        const float4* src = reinterpret_cast<const float4*>(
            g_DS + ((size_t)b * HID + c * CH) * DSP);
        float4* dst = reinterpret_cast<float4*>(SDS);
        #pragma unroll
        for (int q = tid; q < CH * DSP / 4; q += TPB) dst[q] = src[q];
        __syncthreads();

        if (active) {
            #pragma unroll
            for (int ii = 0; ii < CH; ii++) {
                const int i = c * CH + ii;
                float h1 = fmaxf(SDR[i] + SDS[ii * DSP + sidx], 0.f);
                unsigned long long hh = pk2(h1, h1);
                const ulonglong2* w2 =
                    reinterpret_cast<const ulonglong2*>(SW2 + i * H2);
                #pragma unroll
                for (int q = 0; q < 16; q++) {
                    ulonglong2 w = w2[q];
                    fma2(acc2[2 * q],     hh, w.x);
                    fma2(acc2[2 * q + 1], hh, w.y);
                }
            }
        }
    }

    // ---- layer 3: relu(h2) @ fr3 -> E (5 outputs) ----
    float Ek[DE] = {0.f, 0.f, 0.f, 0.f, 0.f};
    if (active) {
        float h2f[H2];
        #pragma unroll
        for (int q = 0; q < H2 / 2; q++) {
            float2 f = upk2(acc2[q]);
            h2f[2 * q]     = fmaxf(f.x, 0.f);
            h2f[2 * q + 1] = fmaxf(f.y, 0.f);
        }
        #pragma unroll
        for (int k = 0; k < DE; k++) {
            float e = SB3[k];
            #pragma unroll
            for (int i2 = 0; i2 < H2; i2++)
                e = fmaf(h2f[i2], SW3T[k * H2 + i2], e);
            Ek[k] = fmaxf(e, 0.f);
        }
    }

    // ---- deterministic block reduction over 187 edges ----
    const int lane = tid & 31, warp = tid >> 5;
    #pragma unroll
    for (int k = 0; k < DE; k++) {
        float v = Ek[k];
        #pragma unroll
        for (int off = 16; off > 0; off >>= 1)
            v += __shfl_down_sync(0xffffffffu, v, off);
        if (lane == 0) SRED[warp * DE + k] = v;
    }
    __syncthreads();
    if (tid < DE) {
        float e = 0.f;
        #pragma unroll
        for (int w = 0; w < 6; w++) e += SRED[w * DE + tid];
        SEBAR[tid] = e;
    }
    __syncthreads();

    // ---- fused object MLP for node (b, r) ----
    if (tid < HID) {
        float a = fo1_b[tid];
        #pragma unroll
        for (int m = 0; m < PF; m++)
            a = fmaf(SXR[m], fo1_w[m * HID + tid], a);
        #pragma unroll
        for (int m = 0; m < DE; m++)
            a = fmaf(SEBAR[m], fo1_w[(PF + m) * HID + tid], a);
        SH1[tid] = fmaxf(a, 0.f);
    }
    __syncthreads();
    if (tid < H2) {
        float a = fo2_b[tid];
        #pragma unroll 8
        for (int m = 0; m < HID; m++)
            a = fmaf(SH1[m], fo2_w[m * H2 + tid], a);
        SH2v[tid] = fmaxf(a, 0.f);
    }
    __syncthreads();
    if (tid < DOUT) {
        float a = fo3_b[tid];
        #pragma unroll
        for (int m = 0; m < H2; m++)
            a = fmaf(SH2v[m], fo3_w[m * DOUT + tid], a);
        g_O[((size_t)b * NC + r) * DOUT + tid] = fmaxf(a, 0.f);
    }
}

// ============================================================================
// Kernel B: FC head. One block per batch, 512 threads, split-K reductions.
// ============================================================================
#define FCT 512
__global__ void __launch_bounds__(FCT) fc_kernel(
    const float* __restrict__ fc1_w, const float* __restrict__ fc1_b,
    const float* __restrict__ fc2_w, const float* __restrict__ fc2_b,
    const float* __restrict__ fc3_w, const float* __restrict__ fc3_b,
    float* __restrict__ out)
{
    __shared__ float sO[NC * DOUT];          // 1128
    __shared__ float sp1[4][HID];
    __shared__ float sh1[HID];
    __shared__ float sp2[8][H2];
    __shared__ float sh2[H2];
    const int b = blockIdx.x, tid = threadIdx.x;

    for (int idx = tid; idx < NC * DOUT; idx += FCT)
        sO[idx] = g_O[(size_t)b * NC * DOUT + idx];
    __syncthreads();

    // fc1: 1128 -> 128, 4-way split over K (282 each)
    {
        const int o = tid & (HID - 1), p = tid >> 7;   // p in 0..3
        const int m0 = p * 282;
        float a = (p == 0) ? fc1_b[o] : 0.f;
        #pragma unroll 6
        for (int m = m0; m < m0 + 282; m++)
            a = fmaf(sO[m], fc1_w[m * HID + o], a);
        sp1[p][o] = a;
    }
    __syncthreads();
    if (tid < HID) {
        float h = sp1[0][tid] + sp1[1][tid] + sp1[2][tid] + sp1[3][tid];
        sh1[tid] = fmaxf(h, 0.f);
    }
    __syncthreads();

    // fc2: 128 -> 64, 8-way split over K (16 each)
    {
        const int o = tid & (H2 - 1), p = tid >> 6;    // p in 0..7
        const int m0 = p * 16;
        float a = (p == 0) ? fc2_b[o] : 0.f;
        #pragma unroll
        for (int m = m0; m < m0 + 16; m++)
            a = fmaf(sh1[m], fc2_w[m * H2 + o], a);
        sp2[p][o] = a;
    }
    __syncthreads();
    if (tid < H2) {
        float h = 0.f;
        #pragma unroll
        for (int p = 0; p < 8; p++) h += sp2[p][tid];
        sh2[tid] = fmaxf(h, 0.f);
    }
    __syncthreads();

    // fc3: 64 -> 5
    if (tid < NT) {
        float a = fc3_b[tid];
        #pragma unroll
        for (int m = 0; m < H2; m++)
            a = fmaf(sh2[m], fc3_w[m * NT + tid], a);
        out[b * NT + tid] = a;
    }
}

// ============================================================================
// Launch
// ============================================================================
extern "C" void kernel_launch(void* const* d_in, const int* in_sizes, int n_in,
                              void* d_out, int out_size) {
    const float* x     = (const float*)d_in[0];
    const float* fr1_w = (const float*)d_in[1];
    const float* fr1_b = (const float*)d_in[2];
    const float* fr2_w = (const float*)d_in[3];
    const float* fr2_b = (const float*)d_in[4];
    const float* fr3_w = (const float*)d_in[5];
    const float* fr3_b = (const float*)d_in[6];
    const float* fo1_w = (const float*)d_in[7];
    const float* fo1_b = (const float*)d_in[8];
    const float* fo2_w = (const float*)d_in[9];
    const float* fo2_b = (const float*)d_in[10];
    const float* fo3_w = (const float*)d_in[11];
    const float* fo3_b = (const float*)d_in[12];
    const float* fc1_w = (const float*)d_in[13];
    const float* fc1_b = (const float*)d_in[14];
    const float* fc2_w = (const float*)d_in[15];
    const float* fc2_b = (const float*)d_in[16];
    const float* fc3_w = (const float*)d_in[17];
    const float* fc3_b = (const float*)d_in[18];
    float* out = (float*)d_out;

    dim3 pgrid(NC, BATCH);
    precompute_kernel<<<pgrid, HID>>>(x, fr1_w, fr1_b);

    dim3 grid(NC, BATCH);
    edge_obj_kernel<<<grid, TPB>>>(x,
                                   fr2_w, fr2_b, fr3_w, fr3_b,
                                   fo1_w, fo1_b, fo2_w, fo2_b, fo3_w, fo3_b);
    fc_kernel<<<BATCH, FCT>>>(fc1_w, fc1_b, fc2_w, fc2_b, fc3_w, fc3_b, out);
}